// round 1
// baseline (speedup 1.0000x reference)
#include <cuda_runtime.h>
#include <cstdint>

#define K_CODES 1024
#define D       256
#define BM      128
#define BN      128
#define DK      64
#define PITCH_X 260   // floats, 16B-aligned rows, avoids conflicts
#define PITCH_E 68    // floats, odd 16B-group stride -> conflict-free LDS.128

__device__ float  g_Se[K_CODES];
__device__ double g_partial[512];

// packed f32x2 fma: acc.lo += a.lo*b.lo ; acc.hi += a.hi*b.hi
#define FMA2(acc, a, b) \
    asm("fma.rn.f32x2 %0, %1, %2, %0;" : "+l"(acc) : "l"(a), "l"(b))

__global__ void se_kernel(const float* __restrict__ cb) {
    int k = blockIdx.x * blockDim.x + threadIdx.x;
    if (k < K_CODES) {
        const float4* r = (const float4*)(cb + k * D);
        float s = 0.f;
        #pragma unroll 4
        for (int i = 0; i < D / 4; i++) {
            float4 v = r[i];
            s += v.x * v.x; s += v.y * v.y; s += v.z * v.z; s += v.w * v.w;
        }
        g_Se[k] = s;
    }
}

extern __shared__ __align__(16) float smem[];

__global__ __launch_bounds__(256, 1)
void vq_kernel(const float* __restrict__ x, const float* __restrict__ cb,
               float* __restrict__ out_q, float* __restrict__ out_idx) {
    float* xs  = smem;                      // BM * PITCH_X
    float* es  = smem + BM * PITCH_X;       // BN * PITCH_E  (reused for reductions)
    float* Ses = es + BN * PITCH_E;         // K_CODES
    float* Sxs = Ses + K_CODES;             // BM
    int*   idxs = (int*)(Sxs + BM);         // BM
    float*  redv = es;                      // BM*16 floats
    int*    redi = (int*)(es + BM * 16);    // BM*16 ints
    double* redd = (double*)es;             // 256 doubles

    const int tid = threadIdx.x;
    const int tx  = tid & 15;
    const int ty  = tid >> 4;
    const int row0 = blockIdx.x * BM;

    // ---- load x tile (full D resident) + Se table ----
    {
        const float4* src = (const float4*)(x + (size_t)row0 * D);
        #pragma unroll 4
        for (int u = 0; u < 32; u++) {
            int f = u * 256 + tid;          // [0, 8192)
            int r = f >> 6, d4 = f & 63;
            float4 v = src[r * 64 + d4];
            *(float4*)(xs + r * PITCH_X + d4 * 4) = v;
        }
        for (int u = tid; u < K_CODES; u += 256) Ses[u] = g_Se[u];
    }
    __syncthreads();

    // ---- per-row Sx = sum(x^2) (fp32, like reference) ----
    if (tid < BM) {
        const float4* r = (const float4*)(xs + tid * PITCH_X);
        float s = 0.f;
        #pragma unroll 4
        for (int i = 0; i < 64; i++) {
            float4 v = r[i];
            s += v.x * v.x; s += v.y * v.y; s += v.z * v.z; s += v.w * v.w;
        }
        Sxs[tid] = s;
    }
    __syncthreads();

    float sx[8];
    #pragma unroll
    for (int i = 0; i < 8; i++) sx[i] = Sxs[ty * 8 + i];

    float minv[8];
    int   mini[8];
    #pragma unroll
    for (int i = 0; i < 8; i++) { minv[i] = 3.4e38f; mini[i] = 0; }

    // ---- main loop: 8 code-tiles of 128 codes ----
    for (int ct = 0; ct < K_CODES / BN; ct++) {
        unsigned long long acc[8][8];
        #pragma unroll
        for (int i = 0; i < 8; i++)
            #pragma unroll
            for (int j = 0; j < 8; j++) acc[i][j] = 0ull;

        for (int dk = 0; dk < D / DK; dk++) {
            __syncthreads();   // previous consumers of es done
            // load codebook chunk: 128 codes x 64 d
            #pragma unroll
            for (int u = 0; u < 8; u++) {
                int f = u * 256 + tid;      // [0, 2048)
                int c = f >> 4, d4 = f & 15;
                float4 v = *(const float4*)(cb + (ct * BN + c) * D + dk * DK + d4 * 4);
                *(float4*)(es + c * PITCH_E + d4 * 4) = v;
            }
            __syncthreads();

            const float* abase = xs + (ty * 8) * PITCH_X + dk * DK;
            const float* bbase = es + tx * PITCH_E;
            #pragma unroll 1
            for (int d4 = 0; d4 < 16; d4++) {
                ulonglong2 A[8], B[8];
                #pragma unroll
                for (int i = 0; i < 8; i++)
                    A[i] = *(const ulonglong2*)(abase + i * PITCH_X + d4 * 4);
                #pragma unroll
                for (int j = 0; j < 8; j++)
                    B[j] = *(const ulonglong2*)(bbase + j * 16 * PITCH_E + d4 * 4);
                #pragma unroll
                for (int i = 0; i < 8; i++)
                    #pragma unroll
                    for (int j = 0; j < 8; j++) {
                        FMA2(acc[i][j], A[i].x, B[j].x);
                        FMA2(acc[i][j], A[i].y, B[j].y);
                    }
            }
        }

        // epilogue: d = (Sx + Se) - 2*dot  (fp32, same grid as reference)
        #pragma unroll
        for (int j = 0; j < 8; j++) {
            int code = ct * BN + j * 16 + tx;
            float se = Ses[code];
            #pragma unroll
            for (int i = 0; i < 8; i++) {
                unsigned long long a = acc[i][j];
                float lo = __uint_as_float((unsigned)(a & 0xffffffffull));
                float hi = __uint_as_float((unsigned)(a >> 32));
                float dot = lo + hi;
                float val = (sx[i] + se) - 2.0f * dot;
                if (val < minv[i]) { minv[i] = val; mini[i] = code; }
            }
        }
    }

    __syncthreads();  // es free -> reuse for reductions
    #pragma unroll
    for (int i = 0; i < 8; i++) {
        redv[(ty * 8 + i) * 16 + tx] = minv[i];
        redi[(ty * 8 + i) * 16 + tx] = mini[i];
    }
    __syncthreads();

    if (tid < BM) {
        float bv = redv[tid * 16];
        int   bi = redi[tid * 16];
        for (int t = 1; t < 16; t++) {
            float v = redv[tid * 16 + t];
            int   c = redi[tid * 16 + t];
            if (v < bv || (v == bv && c < bi)) { bv = v; bi = c; }
        }
        idxs[tid] = bi;
        out_idx[row0 + tid] = (float)bi;
    }
    __syncthreads();

    // ---- quantized output (x + (q - x), fp32 like reference STE) + loss ----
    double lacc = 0.0;
    #pragma unroll 4
    for (int u = 0; u < 32; u++) {
        int f = u * 256 + tid;
        int r = f >> 6, d4 = f & 63;
        float4 q  = *(const float4*)(cb + idxs[r] * D + d4 * 4);
        float4 xv = *(const float4*)(xs + r * PITCH_X + d4 * 4);
        float dx = q.x - xv.x, dy = q.y - xv.y, dz = q.z - xv.z, dw = q.w - xv.w;
        float4 o = make_float4(xv.x + dx, xv.y + dy, xv.z + dz, xv.w + dw);
        *(float4*)(out_q + (size_t)(row0 + r) * D + d4 * 4) = o;
        float s0 = dx * dx, s1 = dy * dy, s2 = dz * dz, s3 = dw * dw;
        lacc += (double)s0 + (double)s1 + (double)s2 + (double)s3;
    }
    __syncthreads();            // done reading redv/redi region
    redd[tid] = lacc;
    __syncthreads();
    for (int s = 128; s > 0; s >>= 1) {   // fixed-order -> deterministic
        if (tid < s) redd[tid] += redd[tid + s];
        __syncthreads();
    }
    if (tid == 0) g_partial[blockIdx.x] = redd[0];
}

__global__ void finish_kernel(float* __restrict__ out_loss, int nblocks, double inv_nd) {
    if (threadIdx.x == 0 && blockIdx.x == 0) {
        double s = 0.0;
        for (int i = 0; i < nblocks; i++) s += g_partial[i];
        *out_loss = (float)(s * inv_nd);
    }
}

extern "C" void kernel_launch(void* const* d_in, const int* in_sizes, int n_in,
                              void* d_out, int out_size) {
    const float* x  = (const float*)d_in[0];
    const float* cb = (const float*)d_in[1];
    float* out = (float*)d_out;

    const int nelem = in_sizes[0];      // 16*2048*256 = 8388608
    const int N     = nelem / D;        // 32768
    const int nblocks = N / BM;         // 256

    float* out_q    = out;
    float* out_idx  = out + nelem;
    float* out_loss = out + nelem + N;

    const int smem_bytes = (BM * PITCH_X + BN * PITCH_E + K_CODES + BM) * 4 + BM * 4;
    cudaFuncSetAttribute(vq_kernel, cudaFuncAttributeMaxDynamicSharedMemorySize, smem_bytes);

    se_kernel<<<(K_CODES + 127) / 128, 128>>>(cb);
    vq_kernel<<<nblocks, 256, smem_bytes>>>(x, cb, out_q, out_idx);
    finish_kernel<<<1, 32>>>(out_loss, nblocks, 1.0 / (double)nelem);
}